// round 1
// baseline (speedup 1.0000x reference)
#include <cuda_runtime.h>

// Problem constants (from reference: B=1024, S=200, Q=512)
#define PB 1024
#define PS 200
#define PQ 512
#define ROWS (PB * (PS - 1))          // 203,776 (b, s+1) rows
#define WARPS_PER_BLOCK 16
#define THREADS (WARPS_PER_BLOCK * 32)

__global__ void init_out_kernel(float* out) {
    if (threadIdx.x == 0) out[0] = 0.0f;
}

// One warp per (b, s1) row with s1 in [1, S).
// Scans batch[b, s1, 0:2Q] (4 KB) in four 1 KB chunks with early exit once the
// single one-hot nonzero is found. Then gathers pred[b, s1-1, qid] and adds
// the log-likelihood term.
__global__ __launch_bounds__(THREADS)
void loss_kernel(const float* __restrict__ pred,
                 const float* __restrict__ batch,
                 float* __restrict__ out)
{
    __shared__ float warpsum[WARPS_PER_BLOCK];

    const int lane   = threadIdx.x & 31;
    const int wlocal = threadIdx.x >> 5;
    const int row    = blockIdx.x * WARPS_PER_BLOCK + wlocal;

    float contrib = 0.0f;

    if (row < ROWS) {
        const int b  = row / (PS - 1);
        const int s1 = row - b * (PS - 1) + 1;      // 1..S-1

        // batch row base: [b, s1, 0], row length 2Q = 1024 floats = 4 KB
        const float4* __restrict__ brow =
            reinterpret_cast<const float4*>(batch + ((size_t)b * PS + s1) * (2 * PQ));

        int idx = -1;   // element index of the nonzero within [0, 2Q)

        // 4 chunks x 1 KB. Each lane loads 2 float4 (32 contiguous bytes).
        #pragma unroll
        for (int c = 0; c < 4; c++) {
            const int v4base = c * 64 + lane * 2;   // float4 index within row
            float4 v0 = brow[v4base + 0];
            float4 v1 = brow[v4base + 1];
            const int e = v4base * 4;               // element index
            if (v0.x != 0.0f) idx = e + 0;
            if (v0.y != 0.0f) idx = e + 1;
            if (v0.z != 0.0f) idx = e + 2;
            if (v0.w != 0.0f) idx = e + 3;
            if (v1.x != 0.0f) idx = e + 4;
            if (v1.y != 0.0f) idx = e + 5;
            if (v1.z != 0.0f) idx = e + 6;
            if (v1.w != 0.0f) idx = e + 7;
            // Early exit: skip remaining chunks once any lane found it.
            if (__ballot_sync(0xffffffffu, idx >= 0)) break;
        }

        // Warp max-reduce the found index to lane 0.
        #pragma unroll
        for (int off = 16; off > 0; off >>= 1)
            idx = max(idx, __shfl_xor_sync(0xffffffffu, idx, off));

        if (lane == 0 && idx >= 0) {
            const int correct = (idx < PQ) ? 1 : 0;
            const int qid     = correct ? idx : (idx - PQ);
            // p = pred[b, s1-1, qid]
            const float p = __ldg(pred + ((size_t)b * PS + (s1 - 1)) * PQ + qid);
            // a = correct; ll = a*log(p) + (1-a)*log(1-p)
            contrib = correct ? logf(p) : logf(1.0f - p);
        }
    }

    if (lane == 0) warpsum[wlocal] = contrib;
    __syncthreads();

    if (threadIdx.x == 0) {
        float s = 0.0f;
        #pragma unroll
        for (int i = 0; i < WARPS_PER_BLOCK; i++) s += warpsum[i];
        atomicAdd(out, -s);   // loss = -sum(ll)
    }
}

extern "C" void kernel_launch(void* const* d_in, const int* in_sizes, int n_in,
                              void* d_out, int out_size)
{
    const float* pred  = (const float*)d_in[0];   // [B, S, Q] fp32
    const float* batch = (const float*)d_in[1];   // [B, S, 2Q] fp32
    float* out = (float*)d_out;                   // [1] fp32

    init_out_kernel<<<1, 32>>>(out);

    const int blocks = (ROWS + WARPS_PER_BLOCK - 1) / WARPS_PER_BLOCK;
    loss_kernel<<<blocks, THREADS>>>(pred, batch, out);
}